// round 13
// baseline (speedup 1.0000x reference)
#include <cuda_runtime.h>
#include <cuda_fp16.h>
#include <cstdint>

// Problem constants
#define NB 128
#define NC 10
#define NR 8192
#define NI 8
#define NO 16

#define RCH 64        // r per block (single smem stage)
#define NPAIR (RCH/2) // r-pairs per block
#define NTHREADS 320  // 10 warps, warp == class c

// Scratch (no cudaMalloc allowed)
__device__ float g_s[3][NB * NC * NO];
__device__ uint4 g_xh[(size_t)NB * NR];         // x fp16: [b][r][8i]
// W fragments pre-packed per (c, r, lane): .x = B-frag word n-tile0, .y = n-tile1
__device__ uint2 g_wht2[(size_t)NC * NR * 32];

// W [C,R,I,O] f32 -> per-lane packed B fragments. Also zeroes g_s.
__global__ void conv_w_kernel(const float* __restrict__ W) {
    int idx = blockIdx.x * blockDim.x + threadIdx.x;   // over NC*NR*32
    if (idx < 3 * NB * NC * NO) (&g_s[0][0])[idx] = 0.0f;
    if (idx >= NC * NR * 32) return;
    int lane = idx & 31;
    int rc   = idx >> 5;                               // c*NR + r
    int gr = lane >> 2, gc = lane & 3;
    const float* base = W + (size_t)rc * (NI * NO);
    float a0 = __ldg(base + (2 * gc) * NO + gr);
    float a1 = __ldg(base + (2 * gc + 1) * NO + gr);
    float b0 = __ldg(base + (2 * gc) * NO + gr + 8);
    float b1 = __ldg(base + (2 * gc + 1) * NO + gr + 8);
    __half2 h0 = __floats2half2_rn(a0, a1);
    __half2 h1 = __floats2half2_rn(b0, b1);
    uint2 v;
    v.x = *(unsigned*)&h0;
    v.y = *(unsigned*)&h1;
    g_wht2[idx] = v;
}

__device__ __forceinline__ void mma_16n8k8(float d[4], unsigned a0, unsigned a1,
                                           unsigned b0) {
    float z = 0.0f;
    asm volatile(
        "mma.sync.aligned.m16n8k8.row.col.f32.f16.f16.f32 "
        "{%0,%1,%2,%3}, {%4,%5}, {%6}, {%7,%8,%9,%10};\n"
        : "=f"(d[0]), "=f"(d[1]), "=f"(d[2]), "=f"(d[3])
        : "r"(a0), "r"(a1), "r"(b0), "f"(z), "f"(z), "f"(z), "f"(z));
}

// k16 accumulate: two independent k8 blocks (two r's) in one MMA.
__device__ __forceinline__ void mma_16n8k16_acc(float d[4],
                                                unsigned a0, unsigned a1,
                                                unsigned a2, unsigned a3,
                                                unsigned b0, unsigned b1) {
    asm volatile(
        "mma.sync.aligned.m16n8k16.row.col.f32.f16.f16.f32 "
        "{%0,%1,%2,%3}, {%4,%5,%6,%7}, {%8,%9}, {%0,%1,%2,%3};\n"
        : "+f"(d[0]), "+f"(d[1]), "+f"(d[2]), "+f"(d[3])
        : "r"(a0), "r"(a1), "r"(a2), "r"(a3), "r"(b0), "r"(b1));
}

__device__ __forceinline__ unsigned hscale(unsigned xw, __half2 wh) {
    __half2 xv = *reinterpret_cast<__half2*>(&xw);
    __half2 r = __hmul2(xv, wh);
    return *reinterpret_cast<unsigned*>(&r);
}

__device__ __forceinline__ uint4 pack_x8(float4 a, float4 b) {
    __half2 h0 = __floats2half2_rn(a.x, a.y);
    __half2 h1 = __floats2half2_rn(a.z, a.w);
    __half2 h2 = __floats2half2_rn(b.x, b.y);
    __half2 h3 = __floats2half2_rn(b.z, b.w);
    uint4 v;
    v.x = *(unsigned*)&h0; v.y = *(unsigned*)&h1;
    v.z = *(unsigned*)&h2; v.w = *(unsigned*)&h3;
    return v;
}

// ---------------------------------------------------------------------------
// Pass 0: uniform weights -> s0 = 0.1 * sum_r u. k16 MMA accumulation.
// Converts x to fp16 (writes g_xh) while staging. grid 512, occ 3.
// ---------------------------------------------------------------------------
__global__ __launch_bounds__(NTHREADS, 3) void pass0_kernel(
    const float* __restrict__ x)
{
    __shared__ uint4 xs[RCH * 32];          // x tile [r][b] swizzled (32 KB)

    const int tid  = threadIdx.x;
    const int lane = tid & 31;
    const int c    = tid >> 5;
    const int b0   = blockIdx.x * 32;
    const int gr   = lane >> 2;
    const int gc   = lane & 3;
    const int r0   = blockIdx.y * RCH;

    float sacc[2][2][4];
    #pragma unroll
    for (int mt = 0; mt < 2; mt++)
        #pragma unroll
        for (int t = 0; t < 2; t++)
            #pragma unroll
            for (int j = 0; j < 4; j++) sacc[mt][t][j] = 0.0f;

    const unsigned xs_base = (unsigned)__cvta_generic_to_shared(xs);
    const uint2* wbc = g_wht2 + (size_t)c * NR * 32;

    for (int i = tid; i < 32 * RCH; i += NTHREADS) {
        int b = i >> 6, r = i & (RCH - 1);
        size_t idx = (size_t)(b0 + b) * NR + r0 + r;
        const float4* p = (const float4*)x + idx * 2;
        uint4 v = pack_x8(__ldg(p), __ldg(p + 1));
        xs[r * 32 + (b ^ (r & 7))] = v;
        g_xh[idx] = v;                      // feed passes 1/2
    }
    __syncthreads();

    #pragma unroll 1
    for (int rr = 0; rr < RCH; rr += 4) {
        unsigned ra[4][4];
        uint2 rbv[4];
        #pragma unroll
        for (int j = 0; j < 4; j++) {
            const int rj = rr + j;
            unsigned amat =
                xs_base + (unsigned)(rj * 32 + (lane ^ (rj & 7))) * 16;
            asm volatile(
                "ldmatrix.sync.aligned.m8n8.x4.shared.b16 "
                "{%0,%1,%2,%3}, [%4];\n"
                : "=r"(ra[j][0]), "=r"(ra[j][1]),
                  "=r"(ra[j][2]), "=r"(ra[j][3]) : "r"(amat));
            rbv[j] = __ldg(&wbc[(size_t)(r0 + rj) * 32 + lane]);
        }
        #pragma unroll
        for (int p = 0; p < 2; p++) {       // r-pairs (j=2p, 2p+1)
            int j0 = 2 * p, j1 = 2 * p + 1;
            mma_16n8k16_acc(sacc[0][0], ra[j0][0], ra[j0][1],
                            ra[j1][0], ra[j1][1], rbv[j0].x, rbv[j1].x);
            mma_16n8k16_acc(sacc[0][1], ra[j0][0], ra[j0][1],
                            ra[j1][0], ra[j1][1], rbv[j0].y, rbv[j1].y);
            mma_16n8k16_acc(sacc[1][0], ra[j0][2], ra[j0][3],
                            ra[j1][2], ra[j1][3], rbv[j0].x, rbv[j1].x);
            mma_16n8k16_acc(sacc[1][1], ra[j0][2], ra[j0][3],
                            ra[j1][2], ra[j1][3], rbv[j0].y, rbv[j1].y);
        }
    }

    float* s = &g_s[0][0];
    #pragma unroll
    for (int mt = 0; mt < 2; mt++)
        #pragma unroll
        for (int t = 0; t < 2; t++) {
            int bA = b0 + mt * 16 + gr;
            int o  = t * 8 + 2 * gc;
            atomicAdd(&s[((size_t)bA * NC + c) * NO + o],     0.1f * sacc[mt][t][0]);
            atomicAdd(&s[((size_t)bA * NC + c) * NO + o + 1], 0.1f * sacc[mt][t][1]);
            atomicAdd(&s[((size_t)(bA + 8) * NC + c) * NO + o],     0.1f * sacc[mt][t][2]);
            atomicAdd(&s[((size_t)(bA + 8) * NC + c) * NO + o + 1], 0.1f * sacc[mt][t][3]);
        }
}

// ---------------------------------------------------------------------------
// Passes 1/2: ONE barrier per r-pair. Iteration k: (pre-bar) compute e for
// pair k; (post-bar) Z-warps produce rz_k while ALL warps consume pair k-1
// (re-ldmatrix its A frags, read its e/rz from smem, z-MMA into sacc).
// Triple-buffered sm_e/sm_rz break the write(k+1)/read(k-1) race.
// Nothing new lives across the barrier except rbv_prev. grid 512, occ 2.
// ---------------------------------------------------------------------------
template <int PASS>
__global__ __launch_bounds__(NTHREADS, 2) void pass_kernel()
{
    __shared__ uint4 xs[RCH * 32];
    __shared__ float sm_e[3][2][NC][32];   // [buf][j][c][row]
    __shared__ float sm_rz[3][2][32];      // [buf][j][row]

    const int tid  = threadIdx.x;
    const int lane = tid & 31;
    const int c    = tid >> 5;
    const int b0   = blockIdx.x * 32;
    const int gr   = lane >> 2;
    const int gc   = lane & 3;
    const int r0   = blockIdx.y * RCH;

    const float LOG2E = 1.4426950408889634f;

    // Prologue: V2[mt][ab][t] = LOG2E * sum_slot squash(s_slot)[b][c][o..o+1]
    float2 V2[2][2][2];
    #pragma unroll
    for (int mt = 0; mt < 2; mt++)
        #pragma unroll
        for (int ab = 0; ab < 2; ab++) {
            V2[mt][ab][0] = make_float2(0.f, 0.f);
            V2[mt][ab][1] = make_float2(0.f, 0.f);
            int b = b0 + mt * 16 + gr + ab * 8;
            const float* sb0 = &g_s[0][((size_t)b * NC + c) * NO];
            #pragma unroll
            for (int slot = 0; slot < PASS; slot++) {
                const float* sp = sb0 + (size_t)slot * (NB * NC * NO);
                float2 s0 = __ldg((const float2*)(sp + 2 * gc));
                float2 s1 = __ldg((const float2*)(sp + 8 + 2 * gc));
                float part = s0.x * s0.x + s0.y * s0.y
                           + s1.x * s1.x + s1.y * s1.y;
                part += __shfl_xor_sync(0xffffffffu, part, 1);
                part += __shfl_xor_sync(0xffffffffu, part, 2);
                float scale = (part / (1.0f + part)) * rsqrtf(part + 1e-8f)
                            * LOG2E;
                V2[mt][ab][0].x += scale * s0.x;
                V2[mt][ab][0].y += scale * s0.y;
                V2[mt][ab][1].x += scale * s1.x;
                V2[mt][ab][1].y += scale * s1.y;
            }
        }

    float sacc[2][2][4];
    #pragma unroll
    for (int mt = 0; mt < 2; mt++)
        #pragma unroll
        for (int t = 0; t < 2; t++)
            #pragma unroll
            for (int j = 0; j < 4; j++) sacc[mt][t][j] = 0.0f;

    const unsigned xs_base = (unsigned)__cvta_generic_to_shared(xs);
    const uint2* wbc = g_wht2 + (size_t)c * NR * 32;

    for (int i = tid; i < 32 * RCH; i += NTHREADS) {
        int b = i >> 6, r = i & (RCH - 1);
        xs[r * 32 + (b ^ (r & 7))] =
            __ldg(&g_xh[(size_t)(b0 + b) * NR + r0 + r]);
    }
    __syncthreads();

    // W fragment pipeline registers: prev (pair k-1), cur (pair k), next.
    uint2 rbv_prev[2], rbv_cur[2], rbv_next[2];
    rbv_cur[0] = __ldg(&wbc[(size_t)r0 * 32 + lane]);
    rbv_cur[1] = __ldg(&wbc[(size_t)(r0 + 1) * 32 + lane]);

    #pragma unroll 1
    for (int k = 0; k <= NPAIR; k++) {
        const int pb = k % 3;            // buffer for pair k
        if (k < NPAIR) {
            // prefetch W for pair k+1
            const int rn = (k + 1 < NPAIR) ? (k + 1) * 2 : k * 2;
            rbv_next[0] = __ldg(&wbc[(size_t)(r0 + rn) * 32 + lane]);
            rbv_next[1] = __ldg(&wbc[(size_t)(r0 + rn + 1) * 32 + lane]);

            // compute e for pair k
            #pragma unroll
            for (int j = 0; j < 2; j++) {
                const int rj = 2 * k + j;
                unsigned ra[4];
                unsigned amat =
                    xs_base + (unsigned)(rj * 32 + (lane ^ (rj & 7))) * 16;
                asm volatile(
                    "ldmatrix.sync.aligned.m8n8.x4.shared.b16 "
                    "{%0,%1,%2,%3}, [%4];\n"
                    : "=r"(ra[0]), "=r"(ra[1]), "=r"(ra[2]), "=r"(ra[3])
                    : "r"(amat));

                float d[2][2][4];
                mma_16n8k8(d[0][0], ra[0], ra[1], rbv_cur[j].x);
                mma_16n8k8(d[0][1], ra[0], ra[1], rbv_cur[j].y);
                mma_16n8k8(d[1][0], ra[2], ra[3], rbv_cur[j].x);
                mma_16n8k8(d[1][1], ra[2], ra[3], rbv_cur[j].y);

                float a[2][2];
                #pragma unroll
                for (int mt = 0; mt < 2; mt++) {
                    a[mt][0] = d[mt][0][0] * V2[mt][0][0].x
                             + d[mt][0][1] * V2[mt][0][0].y
                             + d[mt][1][0] * V2[mt][0][1].x
                             + d[mt][1][1] * V2[mt][0][1].y;
                    a[mt][1] = d[mt][0][2] * V2[mt][1][0].x
                             + d[mt][0][3] * V2[mt][1][0].y
                             + d[mt][1][2] * V2[mt][1][1].x
                             + d[mt][1][3] * V2[mt][1][1].y;
                }
                #pragma unroll
                for (int mt = 0; mt < 2; mt++)
                    #pragma unroll
                    for (int ab = 0; ab < 2; ab++) {
                        a[mt][ab] += __shfl_xor_sync(0xffffffffu, a[mt][ab], 1);
                        a[mt][ab] += __shfl_xor_sync(0xffffffffu, a[mt][ab], 2);
                        if (gc == 0)
                            sm_e[pb][j][c][mt * 16 + gr + ab * 8] =
                                exp2f(a[mt][ab]);
                    }
            }
        }

        __syncthreads();   // e_k visible; rz_{k-1} (written post-bar k-1) visible

        // Z-warps: rz for pair k (overlaps with consumption of pair k-1 below)
        if (k < NPAIR && tid < 64) {
            int j = tid >> 5, bb = tid & 31;
            float Z = 0.0f;
            #pragma unroll
            for (int cc = 0; cc < NC; cc++) Z += sm_e[pb][j][cc][bb];
            sm_rz[pb][j][bb] = __fdividef(1.0f, Z);
        }

        // consume pair k-1
        if (k > 0) {
            const int q = (k - 1) % 3;
            unsigned z[2][4];
            #pragma unroll
            for (int j = 0; j < 2; j++) {
                const int rj = 2 * (k - 1) + j;
                unsigned ra[4];
                unsigned amat =
                    xs_base + (unsigned)(rj * 32 + (lane ^ (rj & 7))) * 16;
                asm volatile(
                    "ldmatrix.sync.aligned.m8n8.x4.shared.b16 "
                    "{%0,%1,%2,%3}, [%4];\n"
                    : "=r"(ra[0]), "=r"(ra[1]), "=r"(ra[2]), "=r"(ra[3])
                    : "r"(amat));

                __half2 wh[2][2];
                #pragma unroll
                for (int mt = 0; mt < 2; mt++)
                    #pragma unroll
                    for (int ab = 0; ab < 2; ab++) {
                        int row = mt * 16 + gr + ab * 8;
                        wh[mt][ab] = __float2half2_rn(
                            sm_e[q][j][c][row] * sm_rz[q][j][row]);
                    }
                z[j][0] = hscale(ra[0], wh[0][0]);
                z[j][1] = hscale(ra[1], wh[0][1]);
                z[j][2] = hscale(ra[2], wh[1][0]);
                z[j][3] = hscale(ra[3], wh[1][1]);
            }
            mma_16n8k16_acc(sacc[0][0], z[0][0], z[0][1], z[1][0], z[1][1],
                            rbv_prev[0].x, rbv_prev[1].x);
            mma_16n8k16_acc(sacc[0][1], z[0][0], z[0][1], z[1][0], z[1][1],
                            rbv_prev[0].y, rbv_prev[1].y);
            mma_16n8k16_acc(sacc[1][0], z[0][2], z[0][3], z[1][2], z[1][3],
                            rbv_prev[0].x, rbv_prev[1].x);
            mma_16n8k16_acc(sacc[1][1], z[0][2], z[0][3], z[1][2], z[1][3],
                            rbv_prev[0].y, rbv_prev[1].y);
        }

        rbv_prev[0] = rbv_cur[0];  rbv_prev[1] = rbv_cur[1];
        rbv_cur[0]  = rbv_next[0]; rbv_cur[1]  = rbv_next[1];
    }

    float* s = &g_s[PASS][0];
    #pragma unroll
    for (int mt = 0; mt < 2; mt++)
        #pragma unroll
        for (int t = 0; t < 2; t++) {
            int bA = b0 + mt * 16 + gr;
            int o  = t * 8 + 2 * gc;
            atomicAdd(&s[((size_t)bA * NC + c) * NO + o],     sacc[mt][t][0]);
            atomicAdd(&s[((size_t)bA * NC + c) * NO + o + 1], sacc[mt][t][1]);
            atomicAdd(&s[((size_t)(bA + 8) * NC + c) * NO + o],     sacc[mt][t][2]);
            atomicAdd(&s[((size_t)(bA + 8) * NC + c) * NO + o + 1], sacc[mt][t][3]);
        }
}

// Final output: v2 = squash(s2)
__global__ void squash_out_kernel(float* __restrict__ out) {
    int idx = blockIdx.x * blockDim.x + threadIdx.x;
    if (idx >= NB * NC) return;

    const float* s = &g_s[2][idx * NO];
    float sv[NO];
    float sq = 0.0f;
    #pragma unroll
    for (int q = 0; q < 4; q++) {
        float4 v = *(const float4*)(s + q * 4);
        sv[q * 4 + 0] = v.x; sv[q * 4 + 1] = v.y;
        sv[q * 4 + 2] = v.z; sv[q * 4 + 3] = v.w;
        sq += v.x * v.x + v.y * v.y + v.z * v.z + v.w * v.w;
    }
    float scale = (sq / (1.0f + sq)) * rsqrtf(sq + 1e-8f);
    #pragma unroll
    for (int o = 0; o < NO; o++) out[idx * NO + o] = scale * sv[o];
}

extern "C" void kernel_launch(void* const* d_in, const int* in_sizes, int n_in,
                              void* d_out, int out_size) {
    const float* x = (const float*)d_in[0];   // [128, 8192, 8]
    const float* W = (const float*)d_in[1];   // [10, 8192, 8, 16]
    float* out = (float*)d_out;               // [128, 10, 16]

    conv_w_kernel<<<(NC * NR * 32 + 255) / 256, 256>>>(W);

    dim3 grid(NB / 32, NR / RCH);             // (4, 128) = 512 blocks
    dim3 sq_grid((NB * NC + 255) / 256);

    pass0_kernel<<<grid, NTHREADS>>>(x);
    pass_kernel<1><<<grid, NTHREADS>>>();
    pass_kernel<2><<<grid, NTHREADS>>>();
    squash_out_kernel<<<sq_grid, 256>>>(out);
}

// round 14
// speedup vs baseline: 1.0158x; 1.0158x over previous
#include <cuda_runtime.h>
#include <cuda_fp16.h>
#include <cstdint>

// Problem constants
#define NB 128
#define NC 10
#define NR 8192
#define NI 8
#define NO 16

#define RCH 64        // r per block (single smem stage)
#define NTHREADS 320  // 10 warps, warp == class c

// Scratch (no cudaMalloc allowed)
__device__ float g_s[3][NB * NC * NO];
__device__ uint4 g_xh[(size_t)NB * NR];         // x fp16: [b][r][8i]
// W fragments pre-packed per (c, r, lane): .x = B-frag word n-tile0, .y = n-tile1
__device__ uint2 g_wht2[(size_t)NC * NR * 32];

// W [C,R,I,O] f32 -> per-lane packed B fragments. Also zeroes g_s.
__global__ void conv_w_kernel(const float* __restrict__ W) {
    int idx = blockIdx.x * blockDim.x + threadIdx.x;   // over NC*NR*32
    if (idx < 3 * NB * NC * NO) (&g_s[0][0])[idx] = 0.0f;
    if (idx >= NC * NR * 32) return;
    int lane = idx & 31;
    int rc   = idx >> 5;                               // c*NR + r
    int gr = lane >> 2, gc = lane & 3;
    const float* base = W + (size_t)rc * (NI * NO);
    float a0 = __ldg(base + (2 * gc) * NO + gr);
    float a1 = __ldg(base + (2 * gc + 1) * NO + gr);
    float b0 = __ldg(base + (2 * gc) * NO + gr + 8);
    float b1 = __ldg(base + (2 * gc + 1) * NO + gr + 8);
    __half2 h0 = __floats2half2_rn(a0, a1);
    __half2 h1 = __floats2half2_rn(b0, b1);
    uint2 v;
    v.x = *(unsigned*)&h0;
    v.y = *(unsigned*)&h1;
    g_wht2[idx] = v;
}

__device__ __forceinline__ void mma_16n8k8(float d[4], unsigned a0, unsigned a1,
                                           unsigned b0) {
    float z = 0.0f;
    asm volatile(
        "mma.sync.aligned.m16n8k8.row.col.f32.f16.f16.f32 "
        "{%0,%1,%2,%3}, {%4,%5}, {%6}, {%7,%8,%9,%10};\n"
        : "=f"(d[0]), "=f"(d[1]), "=f"(d[2]), "=f"(d[3])
        : "r"(a0), "r"(a1), "r"(b0), "f"(z), "f"(z), "f"(z), "f"(z));
}

// k16 accumulate: two independent k8 blocks (two r's) in one MMA.
__device__ __forceinline__ void mma_16n8k16_acc(float d[4],
                                                unsigned a0, unsigned a1,
                                                unsigned a2, unsigned a3,
                                                unsigned b0, unsigned b1) {
    asm volatile(
        "mma.sync.aligned.m16n8k16.row.col.f32.f16.f16.f32 "
        "{%0,%1,%2,%3}, {%4,%5,%6,%7}, {%8,%9}, {%0,%1,%2,%3};\n"
        : "+f"(d[0]), "+f"(d[1]), "+f"(d[2]), "+f"(d[3])
        : "r"(a0), "r"(a1), "r"(a2), "r"(a3), "r"(b0), "r"(b1));
}

__device__ __forceinline__ unsigned hscale(unsigned xw, __half2 wh) {
    __half2 xv = *reinterpret_cast<__half2*>(&xw);
    __half2 r = __hmul2(xv, wh);
    return *reinterpret_cast<unsigned*>(&r);
}

__device__ __forceinline__ uint4 pack_x8(float4 a, float4 b) {
    __half2 h0 = __floats2half2_rn(a.x, a.y);
    __half2 h1 = __floats2half2_rn(a.z, a.w);
    __half2 h2 = __floats2half2_rn(b.x, b.y);
    __half2 h3 = __floats2half2_rn(b.z, b.w);
    uint4 v;
    v.x = *(unsigned*)&h0; v.y = *(unsigned*)&h1;
    v.z = *(unsigned*)&h2; v.w = *(unsigned*)&h3;
    return v;
}

// ---------------------------------------------------------------------------
// Pass 0: uniform weights -> s0 = 0.1 * sum_r u. k16 MMA accumulation.
// Converts x to fp16 (writes g_xh) while staging. grid 512, occ 3.
// ---------------------------------------------------------------------------
__global__ __launch_bounds__(NTHREADS, 3) void pass0_kernel(
    const float* __restrict__ x)
{
    __shared__ uint4 xs[RCH * 32];          // x tile [r][b] swizzled (32 KB)

    const int tid  = threadIdx.x;
    const int lane = tid & 31;
    const int c    = tid >> 5;
    const int b0   = blockIdx.x * 32;
    const int gr   = lane >> 2;
    const int gc   = lane & 3;
    const int r0   = blockIdx.y * RCH;

    float sacc[2][2][4];
    #pragma unroll
    for (int mt = 0; mt < 2; mt++)
        #pragma unroll
        for (int t = 0; t < 2; t++)
            #pragma unroll
            for (int j = 0; j < 4; j++) sacc[mt][t][j] = 0.0f;

    const unsigned xs_base = (unsigned)__cvta_generic_to_shared(xs);
    const uint2* wbc = g_wht2 + (size_t)c * NR * 32;

    for (int i = tid; i < 32 * RCH; i += NTHREADS) {
        int b = i >> 6, r = i & (RCH - 1);
        size_t idx = (size_t)(b0 + b) * NR + r0 + r;
        const float4* p = (const float4*)x + idx * 2;
        uint4 v = pack_x8(__ldg(p), __ldg(p + 1));
        xs[r * 32 + (b ^ (r & 7))] = v;
        g_xh[idx] = v;                      // feed passes 1/2
    }
    __syncthreads();

    #pragma unroll 1
    for (int rr = 0; rr < RCH; rr += 4) {
        unsigned ra[4][4];
        uint2 rbv[4];
        #pragma unroll
        for (int j = 0; j < 4; j++) {
            const int rj = rr + j;
            unsigned amat =
                xs_base + (unsigned)(rj * 32 + (lane ^ (rj & 7))) * 16;
            asm volatile(
                "ldmatrix.sync.aligned.m8n8.x4.shared.b16 "
                "{%0,%1,%2,%3}, [%4];\n"
                : "=r"(ra[j][0]), "=r"(ra[j][1]),
                  "=r"(ra[j][2]), "=r"(ra[j][3]) : "r"(amat));
            rbv[j] = __ldg(&wbc[(size_t)(r0 + rj) * 32 + lane]);
        }
        #pragma unroll
        for (int p = 0; p < 2; p++) {       // r-pairs (j=2p, 2p+1)
            int j0 = 2 * p, j1 = 2 * p + 1;
            mma_16n8k16_acc(sacc[0][0], ra[j0][0], ra[j0][1],
                            ra[j1][0], ra[j1][1], rbv[j0].x, rbv[j1].x);
            mma_16n8k16_acc(sacc[0][1], ra[j0][0], ra[j0][1],
                            ra[j1][0], ra[j1][1], rbv[j0].y, rbv[j1].y);
            mma_16n8k16_acc(sacc[1][0], ra[j0][2], ra[j0][3],
                            ra[j1][2], ra[j1][3], rbv[j0].x, rbv[j1].x);
            mma_16n8k16_acc(sacc[1][1], ra[j0][2], ra[j0][3],
                            ra[j1][2], ra[j1][3], rbv[j0].y, rbv[j1].y);
        }
    }

    float* s = &g_s[0][0];
    #pragma unroll
    for (int mt = 0; mt < 2; mt++)
        #pragma unroll
        for (int t = 0; t < 2; t++) {
            int bA = b0 + mt * 16 + gr;
            int o  = t * 8 + 2 * gc;
            atomicAdd(&s[((size_t)bA * NC + c) * NO + o],     0.1f * sacc[mt][t][0]);
            atomicAdd(&s[((size_t)bA * NC + c) * NO + o + 1], 0.1f * sacc[mt][t][1]);
            atomicAdd(&s[((size_t)(bA + 8) * NC + c) * NO + o],     0.1f * sacc[mt][t][2]);
            atomicAdd(&s[((size_t)(bA + 8) * NC + c) * NO + o + 1], 0.1f * sacc[mt][t][3]);
        }
}

// ---------------------------------------------------------------------------
// Passes 1/2 (round-11 base, distributed softmax): each quad lane owns ONE
// (mt,ab) row — 1 exp instead of 4, 1 STS, ONE barrier per r-pair, then every
// lane sums its own row's 10 e's (conflict-free LDS), w exchanged by 4 quad
// shfls. W prefetch + k16 z-MMA kept. Double-buffered sm_e. grid 512, occ 2.
// ---------------------------------------------------------------------------
template <int PASS>
__global__ __launch_bounds__(NTHREADS, 2) void pass_kernel()
{
    __shared__ uint4 xs[RCH * 32];
    __shared__ float sm_e[2][2][NC][32];   // [buf][j][c][row]

    const int tid  = threadIdx.x;
    const int lane = tid & 31;
    const int c    = tid >> 5;
    const int b0   = blockIdx.x * 32;
    const int gr   = lane >> 2;
    const int gc   = lane & 3;
    const int r0   = blockIdx.y * RCH;

    const float LOG2E = 1.4426950408889634f;

    // Prologue: V2[mt][ab][t] = LOG2E * sum_slot squash(s_slot)[b][c][o..o+1]
    float2 V2[2][2][2];
    #pragma unroll
    for (int mt = 0; mt < 2; mt++)
        #pragma unroll
        for (int ab = 0; ab < 2; ab++) {
            V2[mt][ab][0] = make_float2(0.f, 0.f);
            V2[mt][ab][1] = make_float2(0.f, 0.f);
            int b = b0 + mt * 16 + gr + ab * 8;
            const float* sb0 = &g_s[0][((size_t)b * NC + c) * NO];
            #pragma unroll
            for (int slot = 0; slot < PASS; slot++) {
                const float* sp = sb0 + (size_t)slot * (NB * NC * NO);
                float2 s0 = __ldg((const float2*)(sp + 2 * gc));
                float2 s1 = __ldg((const float2*)(sp + 8 + 2 * gc));
                float part = s0.x * s0.x + s0.y * s0.y
                           + s1.x * s1.x + s1.y * s1.y;
                part += __shfl_xor_sync(0xffffffffu, part, 1);
                part += __shfl_xor_sync(0xffffffffu, part, 2);
                float scale = (part / (1.0f + part)) * rsqrtf(part + 1e-8f)
                            * LOG2E;
                V2[mt][ab][0].x += scale * s0.x;
                V2[mt][ab][0].y += scale * s0.y;
                V2[mt][ab][1].x += scale * s1.x;
                V2[mt][ab][1].y += scale * s1.y;
            }
        }

    float sacc[2][2][4];
    #pragma unroll
    for (int mt = 0; mt < 2; mt++)
        #pragma unroll
        for (int t = 0; t < 2; t++)
            #pragma unroll
            for (int j = 0; j < 4; j++) sacc[mt][t][j] = 0.0f;

    const unsigned xs_base = (unsigned)__cvta_generic_to_shared(xs);
    const uint2* wbc = g_wht2 + (size_t)c * NR * 32;

    for (int i = tid; i < 32 * RCH; i += NTHREADS) {
        int b = i >> 6, r = i & (RCH - 1);
        xs[r * 32 + (b ^ (r & 7))] =
            __ldg(&g_xh[(size_t)(b0 + b) * NR + r0 + r]);
    }
    __syncthreads();

    // lane-owned (mt,ab) row for the distributed softmax
    const int row_mine = (gc >> 1) * 16 + gr + (gc & 1) * 8;

    // preload W fragments for r-pair 0
    uint2 rbv[2];
    rbv[0] = __ldg(&wbc[(size_t)r0 * 32 + lane]);
    rbv[1] = __ldg(&wbc[(size_t)(r0 + 1) * 32 + lane]);

    #pragma unroll 1
    for (int rr = 0; rr < RCH; rr += 2) {
        const int pb = (rr >> 1) & 1;
        // prefetch next r-pair's W BEFORE the barrier
        const int rn = (rr + 2 < RCH) ? rr + 2 : rr;
        uint2 rbn0 = __ldg(&wbc[(size_t)(r0 + rn) * 32 + lane]);
        uint2 rbn1 = __ldg(&wbc[(size_t)(r0 + rn + 1) * 32 + lane]);

        unsigned ra[2][4];
        #pragma unroll
        for (int j = 0; j < 2; j++) {
            const int rj = rr + j;
            unsigned amat =
                xs_base + (unsigned)(rj * 32 + (lane ^ (rj & 7))) * 16;
            asm volatile(
                "ldmatrix.sync.aligned.m8n8.x4.shared.b16 "
                "{%0,%1,%2,%3}, [%4];\n"
                : "=r"(ra[j][0]), "=r"(ra[j][1]),
                  "=r"(ra[j][2]), "=r"(ra[j][3]) : "r"(amat));
        }

        // u via MMA; lane keeps ONLY its own e (1 exp, 1 STS)
        float e_mine[2];
        #pragma unroll
        for (int j = 0; j < 2; j++) {
            float d[2][2][4];
            mma_16n8k8(d[0][0], ra[j][0], ra[j][1], rbv[j].x);
            mma_16n8k8(d[0][1], ra[j][0], ra[j][1], rbv[j].y);
            mma_16n8k8(d[1][0], ra[j][2], ra[j][3], rbv[j].x);
            mma_16n8k8(d[1][1], ra[j][2], ra[j][3], rbv[j].y);

            float a[2][2];
            #pragma unroll
            for (int mt = 0; mt < 2; mt++) {
                a[mt][0] = d[mt][0][0] * V2[mt][0][0].x
                         + d[mt][0][1] * V2[mt][0][0].y
                         + d[mt][1][0] * V2[mt][0][1].x
                         + d[mt][1][1] * V2[mt][0][1].y;
                a[mt][1] = d[mt][0][2] * V2[mt][1][0].x
                         + d[mt][0][3] * V2[mt][1][0].y
                         + d[mt][1][2] * V2[mt][1][1].x
                         + d[mt][1][3] * V2[mt][1][1].y;
            }
            #pragma unroll
            for (int mt = 0; mt < 2; mt++)
                #pragma unroll
                for (int ab = 0; ab < 2; ab++) {
                    a[mt][ab] += __shfl_xor_sync(0xffffffffu, a[mt][ab], 1);
                    a[mt][ab] += __shfl_xor_sync(0xffffffffu, a[mt][ab], 2);
                }
            float am = (gc & 2) ? ((gc & 1) ? a[1][1] : a[1][0])
                                : ((gc & 1) ? a[0][1] : a[0][0]);
            e_mine[j] = exp2f(am);
            sm_e[pb][j][c][row_mine] = e_mine[j];
        }

        __syncthreads();   // ONE barrier per r-pair

        // distributed Z + w exchange, then z-MMA
        unsigned z[2][4];
        #pragma unroll
        for (int j = 0; j < 2; j++) {
            float Z = 0.0f;
            #pragma unroll
            for (int cc = 0; cc < NC; cc++)
                Z += sm_e[pb][j][cc][row_mine];
            float wm = __fdividef(e_mine[j], Z);

            __half2 wh[2][2];
            #pragma unroll
            for (int mt = 0; mt < 2; mt++)
                #pragma unroll
                for (int ab = 0; ab < 2; ab++)
                    wh[mt][ab] = __float2half2_rn(__shfl_sync(
                        0xffffffffu, wm, (lane & ~3) | (mt * 2 + ab)));

            z[j][0] = hscale(ra[j][0], wh[0][0]);
            z[j][1] = hscale(ra[j][1], wh[0][1]);
            z[j][2] = hscale(ra[j][2], wh[1][0]);
            z[j][3] = hscale(ra[j][3], wh[1][1]);
        }
        mma_16n8k16_acc(sacc[0][0], z[0][0], z[0][1], z[1][0], z[1][1],
                        rbv[0].x, rbv[1].x);
        mma_16n8k16_acc(sacc[0][1], z[0][0], z[0][1], z[1][0], z[1][1],
                        rbv[0].y, rbv[1].y);
        mma_16n8k16_acc(sacc[1][0], z[0][2], z[0][3], z[1][2], z[1][3],
                        rbv[0].x, rbv[1].x);
        mma_16n8k16_acc(sacc[1][1], z[0][2], z[0][3], z[1][2], z[1][3],
                        rbv[0].y, rbv[1].y);

        rbv[0] = rbn0;
        rbv[1] = rbn1;
    }

    float* s = &g_s[PASS][0];
    #pragma unroll
    for (int mt = 0; mt < 2; mt++)
        #pragma unroll
        for (int t = 0; t < 2; t++) {
            int bA = b0 + mt * 16 + gr;
            int o  = t * 8 + 2 * gc;
            atomicAdd(&s[((size_t)bA * NC + c) * NO + o],     sacc[mt][t][0]);
            atomicAdd(&s[((size_t)bA * NC + c) * NO + o + 1], sacc[mt][t][1]);
            atomicAdd(&s[((size_t)(bA + 8) * NC + c) * NO + o],     sacc[mt][t][2]);
            atomicAdd(&s[((size_t)(bA + 8) * NC + c) * NO + o + 1], sacc[mt][t][3]);
        }
}

// Final output: v2 = squash(s2)
__global__ void squash_out_kernel(float* __restrict__ out) {
    int idx = blockIdx.x * blockDim.x + threadIdx.x;
    if (idx >= NB * NC) return;

    const float* s = &g_s[2][idx * NO];
    float sv[NO];
    float sq = 0.0f;
    #pragma unroll
    for (int q = 0; q < 4; q++) {
        float4 v = *(const float4*)(s + q * 4);
        sv[q * 4 + 0] = v.x; sv[q * 4 + 1] = v.y;
        sv[q * 4 + 2] = v.z; sv[q * 4 + 3] = v.w;
        sq += v.x * v.x + v.y * v.y + v.z * v.z + v.w * v.w;
    }
    float scale = (sq / (1.0f + sq)) * rsqrtf(sq + 1e-8f);
    #pragma unroll
    for (int o = 0; o < NO; o++) out[idx * NO + o] = scale * sv[o];
}

extern "C" void kernel_launch(void* const* d_in, const int* in_sizes, int n_in,
                              void* d_out, int out_size) {
    const float* x = (const float*)d_in[0];   // [128, 8192, 8]
    const float* W = (const float*)d_in[1];   // [10, 8192, 8, 16]
    float* out = (float*)d_out;               // [128, 10, 16]

    conv_w_kernel<<<(NC * NR * 32 + 255) / 256, 256>>>(W);

    dim3 grid(NB / 32, NR / RCH);             // (4, 128) = 512 blocks
    dim3 sq_grid((NB * NC + 255) / 256);

    pass0_kernel<<<grid, NTHREADS>>>(x);
    pass_kernel<1><<<grid, NTHREADS>>>();
    pass_kernel<2><<<grid, NTHREADS>>>();
    squash_out_kernel<<<sq_grid, 256>>>(out);
}

// round 15
// speedup vs baseline: 1.1638x; 1.1457x over previous
#include <cuda_runtime.h>
#include <cuda_fp16.h>
#include <cstdint>

// Problem constants
#define NB 128
#define NC 10
#define NR 8192
#define NI 8
#define NO 16

#define RCH 64        // r per block (single smem stage)
#define NTHREADS 320  // 10 warps, warp == class c

// Scratch (no cudaMalloc allowed)
__device__ float g_s[3][NB * NC * NO];
__device__ uint4 g_xh[(size_t)NB * NR];         // x fp16: [b][r][8i]
// W fragments pre-packed per (c, r, lane): .x = B-frag word n-tile0, .y = n-tile1
__device__ uint2 g_wht2[(size_t)NC * NR * 32];

// W [C,R,I,O] f32 -> per-lane packed B fragments. Also zeroes g_s.
__global__ void conv_w_kernel(const float* __restrict__ W) {
    int idx = blockIdx.x * blockDim.x + threadIdx.x;   // over NC*NR*32
    if (idx < 3 * NB * NC * NO) (&g_s[0][0])[idx] = 0.0f;
    if (idx >= NC * NR * 32) return;
    int lane = idx & 31;
    int rc   = idx >> 5;                               // c*NR + r
    int gr = lane >> 2, gc = lane & 3;
    const float* base = W + (size_t)rc * (NI * NO);
    float a0 = __ldg(base + (2 * gc) * NO + gr);
    float a1 = __ldg(base + (2 * gc + 1) * NO + gr);
    float b0 = __ldg(base + (2 * gc) * NO + gr + 8);
    float b1 = __ldg(base + (2 * gc + 1) * NO + gr + 8);
    __half2 h0 = __floats2half2_rn(a0, a1);
    __half2 h1 = __floats2half2_rn(b0, b1);
    uint2 v;
    v.x = *(unsigned*)&h0;
    v.y = *(unsigned*)&h1;
    g_wht2[idx] = v;
}

__device__ __forceinline__ void mma_16n8k8(float d[4], unsigned a0, unsigned a1,
                                           unsigned b0) {
    float z = 0.0f;
    asm volatile(
        "mma.sync.aligned.m16n8k8.row.col.f32.f16.f16.f32 "
        "{%0,%1,%2,%3}, {%4,%5}, {%6}, {%7,%8,%9,%10};\n"
        : "=f"(d[0]), "=f"(d[1]), "=f"(d[2]), "=f"(d[3])
        : "r"(a0), "r"(a1), "r"(b0), "f"(z), "f"(z), "f"(z), "f"(z));
}

// k16 accumulate: two independent k8 blocks (two r's) in one MMA.
__device__ __forceinline__ void mma_16n8k16_acc(float d[4],
                                                unsigned a0, unsigned a1,
                                                unsigned a2, unsigned a3,
                                                unsigned b0, unsigned b1) {
    asm volatile(
        "mma.sync.aligned.m16n8k16.row.col.f32.f16.f16.f32 "
        "{%0,%1,%2,%3}, {%4,%5,%6,%7}, {%8,%9}, {%0,%1,%2,%3};\n"
        : "+f"(d[0]), "+f"(d[1]), "+f"(d[2]), "+f"(d[3])
        : "r"(a0), "r"(a1), "r"(a2), "r"(a3), "r"(b0), "r"(b1));
}

__device__ __forceinline__ unsigned hscale(unsigned xw, __half2 wh) {
    __half2 xv = *reinterpret_cast<__half2*>(&xw);
    __half2 r = __hmul2(xv, wh);
    return *reinterpret_cast<unsigned*>(&r);
}

__device__ __forceinline__ uint4 pack_x8(float4 a, float4 b) {
    __half2 h0 = __floats2half2_rn(a.x, a.y);
    __half2 h1 = __floats2half2_rn(a.z, a.w);
    __half2 h2 = __floats2half2_rn(b.x, b.y);
    __half2 h3 = __floats2half2_rn(b.z, b.w);
    uint4 v;
    v.x = *(unsigned*)&h0; v.y = *(unsigned*)&h1;
    v.z = *(unsigned*)&h2; v.w = *(unsigned*)&h3;
    return v;
}

// ---------------------------------------------------------------------------
// Pass 0: uniform weights -> s0 = 0.1 * sum_r u. k16 MMA accumulation.
// Converts x to fp16 (writes g_xh) while staging. grid 512, occ 3.
// ---------------------------------------------------------------------------
__global__ __launch_bounds__(NTHREADS, 3) void pass0_kernel(
    const float* __restrict__ x)
{
    __shared__ uint4 xs[RCH * 32];          // x tile [r][b] swizzled (32 KB)

    const int tid  = threadIdx.x;
    const int lane = tid & 31;
    const int c    = tid >> 5;
    const int b0   = blockIdx.x * 32;
    const int gr   = lane >> 2;
    const int gc   = lane & 3;
    const int r0   = blockIdx.y * RCH;

    float sacc[2][2][4];
    #pragma unroll
    for (int mt = 0; mt < 2; mt++)
        #pragma unroll
        for (int t = 0; t < 2; t++)
            #pragma unroll
            for (int j = 0; j < 4; j++) sacc[mt][t][j] = 0.0f;

    const unsigned xs_base = (unsigned)__cvta_generic_to_shared(xs);
    const uint2* wbc = g_wht2 + (size_t)c * NR * 32;

    for (int i = tid; i < 32 * RCH; i += NTHREADS) {
        int b = i >> 6, r = i & (RCH - 1);
        size_t idx = (size_t)(b0 + b) * NR + r0 + r;
        const float4* p = (const float4*)x + idx * 2;
        uint4 v = pack_x8(__ldg(p), __ldg(p + 1));
        xs[r * 32 + (b ^ (r & 7))] = v;
        g_xh[idx] = v;                      // feed passes 1/2
    }
    __syncthreads();

    #pragma unroll 1
    for (int rr = 0; rr < RCH; rr += 4) {
        unsigned ra[4][4];
        uint2 rbv[4];
        #pragma unroll
        for (int j = 0; j < 4; j++) {
            const int rj = rr + j;
            unsigned amat =
                xs_base + (unsigned)(rj * 32 + (lane ^ (rj & 7))) * 16;
            asm volatile(
                "ldmatrix.sync.aligned.m8n8.x4.shared.b16 "
                "{%0,%1,%2,%3}, [%4];\n"
                : "=r"(ra[j][0]), "=r"(ra[j][1]),
                  "=r"(ra[j][2]), "=r"(ra[j][3]) : "r"(amat));
            rbv[j] = __ldg(&wbc[(size_t)(r0 + rj) * 32 + lane]);
        }
        #pragma unroll
        for (int p = 0; p < 2; p++) {       // r-pairs (j=2p, 2p+1)
            int j0 = 2 * p, j1 = 2 * p + 1;
            mma_16n8k16_acc(sacc[0][0], ra[j0][0], ra[j0][1],
                            ra[j1][0], ra[j1][1], rbv[j0].x, rbv[j1].x);
            mma_16n8k16_acc(sacc[0][1], ra[j0][0], ra[j0][1],
                            ra[j1][0], ra[j1][1], rbv[j0].y, rbv[j1].y);
            mma_16n8k16_acc(sacc[1][0], ra[j0][2], ra[j0][3],
                            ra[j1][2], ra[j1][3], rbv[j0].x, rbv[j1].x);
            mma_16n8k16_acc(sacc[1][1], ra[j0][2], ra[j0][3],
                            ra[j1][2], ra[j1][3], rbv[j0].y, rbv[j1].y);
        }
    }

    float* s = &g_s[0][0];
    #pragma unroll
    for (int mt = 0; mt < 2; mt++)
        #pragma unroll
        for (int t = 0; t < 2; t++) {
            int bA = b0 + mt * 16 + gr;
            int o  = t * 8 + 2 * gc;
            atomicAdd(&s[((size_t)bA * NC + c) * NO + o],     0.1f * sacc[mt][t][0]);
            atomicAdd(&s[((size_t)bA * NC + c) * NO + o + 1], 0.1f * sacc[mt][t][1]);
            atomicAdd(&s[((size_t)(bA + 8) * NC + c) * NO + o],     0.1f * sacc[mt][t][2]);
            atomicAdd(&s[((size_t)(bA + 8) * NC + c) * NO + o + 1], 0.1f * sacc[mt][t][3]);
        }
}

// ---------------------------------------------------------------------------
// Passes 1/2 (round-11 structure, distributed exp): after the quad shfl
// reduction each lane computes exp2f for ONLY its own row (2 MUFU per r-pair
// instead of 8) and all 32 lanes store e with one conflict-free STS. Z-warps
// between two barriers and the W-prefetch + k16 z-MMA are unchanged. w is
// formed from smem e * rz. grid 512, occ 2.
// ---------------------------------------------------------------------------
template <int PASS>
__global__ __launch_bounds__(NTHREADS, 2) void pass_kernel()
{
    __shared__ uint4 xs[RCH * 32];
    __shared__ float sm_e[2][NC][32];
    __shared__ float sm_rz[2][32];

    const int tid  = threadIdx.x;
    const int lane = tid & 31;
    const int c    = tid >> 5;
    const int b0   = blockIdx.x * 32;
    const int gr   = lane >> 2;
    const int gc   = lane & 3;
    const int r0   = blockIdx.y * RCH;

    const float LOG2E = 1.4426950408889634f;

    // Prologue: V2[mt][ab][t] = LOG2E * sum_slot squash(s_slot)[b][c][o..o+1]
    float2 V2[2][2][2];
    #pragma unroll
    for (int mt = 0; mt < 2; mt++)
        #pragma unroll
        for (int ab = 0; ab < 2; ab++) {
            V2[mt][ab][0] = make_float2(0.f, 0.f);
            V2[mt][ab][1] = make_float2(0.f, 0.f);
            int b = b0 + mt * 16 + gr + ab * 8;
            const float* sb0 = &g_s[0][((size_t)b * NC + c) * NO];
            #pragma unroll
            for (int slot = 0; slot < PASS; slot++) {
                const float* sp = sb0 + (size_t)slot * (NB * NC * NO);
                float2 s0 = __ldg((const float2*)(sp + 2 * gc));
                float2 s1 = __ldg((const float2*)(sp + 8 + 2 * gc));
                float part = s0.x * s0.x + s0.y * s0.y
                           + s1.x * s1.x + s1.y * s1.y;
                part += __shfl_xor_sync(0xffffffffu, part, 1);
                part += __shfl_xor_sync(0xffffffffu, part, 2);
                float scale = (part / (1.0f + part)) * rsqrtf(part + 1e-8f)
                            * LOG2E;
                V2[mt][ab][0].x += scale * s0.x;
                V2[mt][ab][0].y += scale * s0.y;
                V2[mt][ab][1].x += scale * s1.x;
                V2[mt][ab][1].y += scale * s1.y;
            }
        }

    float sacc[2][2][4];
    #pragma unroll
    for (int mt = 0; mt < 2; mt++)
        #pragma unroll
        for (int t = 0; t < 2; t++)
            #pragma unroll
            for (int j = 0; j < 4; j++) sacc[mt][t][j] = 0.0f;

    const unsigned xs_base = (unsigned)__cvta_generic_to_shared(xs);
    const uint2* wbc = g_wht2 + (size_t)c * NR * 32;

    for (int i = tid; i < 32 * RCH; i += NTHREADS) {
        int b = i >> 6, r = i & (RCH - 1);
        xs[r * 32 + (b ^ (r & 7))] =
            __ldg(&g_xh[(size_t)(b0 + b) * NR + r0 + r]);
    }
    __syncthreads();

    // lane-owned row for the distributed exp
    const int row_mine = (gc >> 1) * 16 + gr + (gc & 1) * 8;

    // preload W fragments for r-pair 0
    uint2 rbv[2];
    rbv[0] = __ldg(&wbc[(size_t)r0 * 32 + lane]);
    rbv[1] = __ldg(&wbc[(size_t)(r0 + 1) * 32 + lane]);

    #pragma unroll 1
    for (int rr = 0; rr < RCH; rr += 2) {
        // prefetch next r-pair's W BEFORE the softmax/barriers
        const int rn = (rr + 2 < RCH) ? rr + 2 : rr;
        uint2 rbn0 = __ldg(&wbc[(size_t)(r0 + rn) * 32 + lane]);
        uint2 rbn1 = __ldg(&wbc[(size_t)(r0 + rn + 1) * 32 + lane]);

        unsigned ra[2][4];
        #pragma unroll
        for (int j = 0; j < 2; j++) {
            const int rj = rr + j;
            unsigned amat =
                xs_base + (unsigned)(rj * 32 + (lane ^ (rj & 7))) * 16;
            asm volatile(
                "ldmatrix.sync.aligned.m8n8.x4.shared.b16 "
                "{%0,%1,%2,%3}, [%4];\n"
                : "=r"(ra[j][0]), "=r"(ra[j][1]),
                  "=r"(ra[j][2]), "=r"(ra[j][3]) : "r"(amat));
        }

        // u via MMA; d dies right after the logit dot; ONE exp per lane per j
        #pragma unroll
        for (int j = 0; j < 2; j++) {
            float d[2][2][4];
            mma_16n8k8(d[0][0], ra[j][0], ra[j][1], rbv[j].x);
            mma_16n8k8(d[0][1], ra[j][0], ra[j][1], rbv[j].y);
            mma_16n8k8(d[1][0], ra[j][2], ra[j][3], rbv[j].x);
            mma_16n8k8(d[1][1], ra[j][2], ra[j][3], rbv[j].y);

            float a[2][2];
            #pragma unroll
            for (int mt = 0; mt < 2; mt++) {
                a[mt][0] = d[mt][0][0] * V2[mt][0][0].x
                         + d[mt][0][1] * V2[mt][0][0].y
                         + d[mt][1][0] * V2[mt][0][1].x
                         + d[mt][1][1] * V2[mt][0][1].y;
                a[mt][1] = d[mt][0][2] * V2[mt][1][0].x
                         + d[mt][0][3] * V2[mt][1][0].y
                         + d[mt][1][2] * V2[mt][1][1].x
                         + d[mt][1][3] * V2[mt][1][1].y;
            }
            #pragma unroll
            for (int mt = 0; mt < 2; mt++)
                #pragma unroll
                for (int ab = 0; ab < 2; ab++) {
                    a[mt][ab] += __shfl_xor_sync(0xffffffffu, a[mt][ab], 1);
                    a[mt][ab] += __shfl_xor_sync(0xffffffffu, a[mt][ab], 2);
                }
            float am0 = (gc & 1) ? a[0][1] : a[0][0];
            float am1 = (gc & 1) ? a[1][1] : a[1][0];
            float am  = (gc & 2) ? am1 : am0;
            sm_e[j][c][row_mine] = exp2f(am);
        }
        __syncthreads();

        if (tid < 64) {
            int j = tid >> 5, bb = tid & 31;
            float Z = 0.0f;
            #pragma unroll
            for (int k = 0; k < NC; k++) Z += sm_e[j][k][bb];
            sm_rz[j][bb] = __fdividef(1.0f, Z);
        }
        __syncthreads();

        // z = w * x fragments (w = e * rz from smem); k16 z-MMA
        unsigned z[2][4];
        #pragma unroll
        for (int j = 0; j < 2; j++) {
            __half2 wh[2][2];
            #pragma unroll
            for (int mt = 0; mt < 2; mt++)
                #pragma unroll
                for (int ab = 0; ab < 2; ab++) {
                    int row = mt * 16 + gr + ab * 8;
                    wh[mt][ab] = __float2half2_rn(
                        sm_e[j][c][row] * sm_rz[j][row]);
                }
            z[j][0] = hscale(ra[j][0], wh[0][0]);
            z[j][1] = hscale(ra[j][1], wh[0][1]);
            z[j][2] = hscale(ra[j][2], wh[1][0]);
            z[j][3] = hscale(ra[j][3], wh[1][1]);
        }
        mma_16n8k16_acc(sacc[0][0], z[0][0], z[0][1], z[1][0], z[1][1],
                        rbv[0].x, rbv[1].x);
        mma_16n8k16_acc(sacc[0][1], z[0][0], z[0][1], z[1][0], z[1][1],
                        rbv[0].y, rbv[1].y);
        mma_16n8k16_acc(sacc[1][0], z[0][2], z[0][3], z[1][2], z[1][3],
                        rbv[0].x, rbv[1].x);
        mma_16n8k16_acc(sacc[1][1], z[0][2], z[0][3], z[1][2], z[1][3],
                        rbv[0].y, rbv[1].y);

        rbv[0] = rbn0;
        rbv[1] = rbn1;
    }

    float* s = &g_s[PASS][0];
    #pragma unroll
    for (int mt = 0; mt < 2; mt++)
        #pragma unroll
        for (int t = 0; t < 2; t++) {
            int bA = b0 + mt * 16 + gr;
            int o  = t * 8 + 2 * gc;
            atomicAdd(&s[((size_t)bA * NC + c) * NO + o],     sacc[mt][t][0]);
            atomicAdd(&s[((size_t)bA * NC + c) * NO + o + 1], sacc[mt][t][1]);
            atomicAdd(&s[((size_t)(bA + 8) * NC + c) * NO + o],     sacc[mt][t][2]);
            atomicAdd(&s[((size_t)(bA + 8) * NC + c) * NO + o + 1], sacc[mt][t][3]);
        }
}

// Final output: v2 = squash(s2)
__global__ void squash_out_kernel(float* __restrict__ out) {
    int idx = blockIdx.x * blockDim.x + threadIdx.x;
    if (idx >= NB * NC) return;

    const float* s = &g_s[2][idx * NO];
    float sv[NO];
    float sq = 0.0f;
    #pragma unroll
    for (int q = 0; q < 4; q++) {
        float4 v = *(const float4*)(s + q * 4);
        sv[q * 4 + 0] = v.x; sv[q * 4 + 1] = v.y;
        sv[q * 4 + 2] = v.z; sv[q * 4 + 3] = v.w;
        sq += v.x * v.x + v.y * v.y + v.z * v.z + v.w * v.w;
    }
    float scale = (sq / (1.0f + sq)) * rsqrtf(sq + 1e-8f);
    #pragma unroll
    for (int o = 0; o < NO; o++) out[idx * NO + o] = scale * sv[o];
}

extern "C" void kernel_launch(void* const* d_in, const int* in_sizes, int n_in,
                              void* d_out, int out_size) {
    const float* x = (const float*)d_in[0];   // [128, 8192, 8]
    const float* W = (const float*)d_in[1];   // [10, 8192, 8, 16]
    float* out = (float*)d_out;               // [128, 10, 16]

    conv_w_kernel<<<(NC * NR * 32 + 255) / 256, 256>>>(W);

    dim3 grid(NB / 32, NR / RCH);             // (4, 128) = 512 blocks
    dim3 sq_grid((NB * NC + 255) / 256);

    pass0_kernel<<<grid, NTHREADS>>>(x);
    pass_kernel<1><<<grid, NTHREADS>>>();
    pass_kernel<2><<<grid, NTHREADS>>>();
    squash_out_kernel<<<sq_grid, 256>>>(out);
}

// round 16
// speedup vs baseline: 1.1890x; 1.0216x over previous
#include <cuda_runtime.h>
#include <cuda_fp16.h>
#include <cstdint>

// Problem constants
#define NB 128
#define NC 10
#define NR 8192
#define NI 8
#define NO 16

#define RCH 64        // r per block (single smem stage)
#define NTHREADS 320  // 10 warps, warp == class c

// Scratch (no cudaMalloc allowed)
__device__ float g_s[3][NB * NC * NO];
__device__ uint4 g_xh[(size_t)NB * NR];         // x fp16: [b][r][8i]
// W fragments pre-packed per (c, r, lane): .x = B-frag word n-tile0, .y = n-tile1
__device__ uint2 g_wht2[(size_t)NC * NR * 32];

// W [C,R,I,O] f32 -> per-lane packed B fragments. Also zeroes g_s.
__global__ void conv_w_kernel(const float* __restrict__ W) {
    int idx = blockIdx.x * blockDim.x + threadIdx.x;   // over NC*NR*32
    if (idx < 3 * NB * NC * NO) (&g_s[0][0])[idx] = 0.0f;
    if (idx >= NC * NR * 32) return;
    int lane = idx & 31;
    int rc   = idx >> 5;                               // c*NR + r
    int gr = lane >> 2, gc = lane & 3;
    const float* base = W + (size_t)rc * (NI * NO);
    float a0 = __ldg(base + (2 * gc) * NO + gr);
    float a1 = __ldg(base + (2 * gc + 1) * NO + gr);
    float b0 = __ldg(base + (2 * gc) * NO + gr + 8);
    float b1 = __ldg(base + (2 * gc + 1) * NO + gr + 8);
    __half2 h0 = __floats2half2_rn(a0, a1);
    __half2 h1 = __floats2half2_rn(b0, b1);
    uint2 v;
    v.x = *(unsigned*)&h0;
    v.y = *(unsigned*)&h1;
    g_wht2[idx] = v;
}

__device__ __forceinline__ void mma_16n8k8(float d[4], unsigned a0, unsigned a1,
                                           unsigned b0) {
    float z = 0.0f;
    asm volatile(
        "mma.sync.aligned.m16n8k8.row.col.f32.f16.f16.f32 "
        "{%0,%1,%2,%3}, {%4,%5}, {%6}, {%7,%8,%9,%10};\n"
        : "=f"(d[0]), "=f"(d[1]), "=f"(d[2]), "=f"(d[3])
        : "r"(a0), "r"(a1), "r"(b0), "f"(z), "f"(z), "f"(z), "f"(z));
}

// k16 accumulate: two independent k8 blocks (two r's) in one MMA.
__device__ __forceinline__ void mma_16n8k16_acc(float d[4],
                                                unsigned a0, unsigned a1,
                                                unsigned a2, unsigned a3,
                                                unsigned b0, unsigned b1) {
    asm volatile(
        "mma.sync.aligned.m16n8k16.row.col.f32.f16.f16.f32 "
        "{%0,%1,%2,%3}, {%4,%5,%6,%7}, {%8,%9}, {%0,%1,%2,%3};\n"
        : "+f"(d[0]), "+f"(d[1]), "+f"(d[2]), "+f"(d[3])
        : "r"(a0), "r"(a1), "r"(a2), "r"(a3), "r"(b0), "r"(b1));
}

__device__ __forceinline__ unsigned hscale(unsigned xw, __half2 wh) {
    __half2 xv = *reinterpret_cast<__half2*>(&xw);
    __half2 r = __hmul2(xv, wh);
    return *reinterpret_cast<unsigned*>(&r);
}

__device__ __forceinline__ uint4 pack_x8(float4 a, float4 b) {
    __half2 h0 = __floats2half2_rn(a.x, a.y);
    __half2 h1 = __floats2half2_rn(a.z, a.w);
    __half2 h2 = __floats2half2_rn(b.x, b.y);
    __half2 h3 = __floats2half2_rn(b.z, b.w);
    uint4 v;
    v.x = *(unsigned*)&h0; v.y = *(unsigned*)&h1;
    v.z = *(unsigned*)&h2; v.w = *(unsigned*)&h3;
    return v;
}

// ---------------------------------------------------------------------------
// Pass 0: uniform weights -> s0 = 0.1 * sum_r u. k16 MMA accumulation.
// Converts x to fp16 (writes g_xh) while staging. grid 512, occ 3.
// ---------------------------------------------------------------------------
__global__ __launch_bounds__(NTHREADS, 3) void pass0_kernel(
    const float* __restrict__ x)
{
    __shared__ uint4 xs[RCH * 32];          // x tile [r][b] swizzled (32 KB)

    const int tid  = threadIdx.x;
    const int lane = tid & 31;
    const int c    = tid >> 5;
    const int b0   = blockIdx.x * 32;
    const int gr   = lane >> 2;
    const int gc   = lane & 3;
    const int r0   = blockIdx.y * RCH;

    float sacc[2][2][4];
    #pragma unroll
    for (int mt = 0; mt < 2; mt++)
        #pragma unroll
        for (int t = 0; t < 2; t++)
            #pragma unroll
            for (int j = 0; j < 4; j++) sacc[mt][t][j] = 0.0f;

    const unsigned xs_base = (unsigned)__cvta_generic_to_shared(xs);
    const uint2* wbc = g_wht2 + (size_t)c * NR * 32;

    for (int i = tid; i < 32 * RCH; i += NTHREADS) {
        int b = i >> 6, r = i & (RCH - 1);
        size_t idx = (size_t)(b0 + b) * NR + r0 + r;
        const float4* p = (const float4*)x + idx * 2;
        uint4 v = pack_x8(__ldg(p), __ldg(p + 1));
        xs[r * 32 + (b ^ (r & 7))] = v;
        g_xh[idx] = v;                      // feed passes 1/2
    }
    __syncthreads();

    #pragma unroll 1
    for (int rr = 0; rr < RCH; rr += 4) {
        unsigned ra[4][4];
        uint2 rbv[4];
        #pragma unroll
        for (int j = 0; j < 4; j++) {
            const int rj = rr + j;
            unsigned amat =
                xs_base + (unsigned)(rj * 32 + (lane ^ (rj & 7))) * 16;
            asm volatile(
                "ldmatrix.sync.aligned.m8n8.x4.shared.b16 "
                "{%0,%1,%2,%3}, [%4];\n"
                : "=r"(ra[j][0]), "=r"(ra[j][1]),
                  "=r"(ra[j][2]), "=r"(ra[j][3]) : "r"(amat));
            rbv[j] = __ldg(&wbc[(size_t)(r0 + rj) * 32 + lane]);
        }
        #pragma unroll
        for (int p = 0; p < 2; p++) {       // r-pairs (j=2p, 2p+1)
            int j0 = 2 * p, j1 = 2 * p + 1;
            mma_16n8k16_acc(sacc[0][0], ra[j0][0], ra[j0][1],
                            ra[j1][0], ra[j1][1], rbv[j0].x, rbv[j1].x);
            mma_16n8k16_acc(sacc[0][1], ra[j0][0], ra[j0][1],
                            ra[j1][0], ra[j1][1], rbv[j0].y, rbv[j1].y);
            mma_16n8k16_acc(sacc[1][0], ra[j0][2], ra[j0][3],
                            ra[j1][2], ra[j1][3], rbv[j0].x, rbv[j1].x);
            mma_16n8k16_acc(sacc[1][1], ra[j0][2], ra[j0][3],
                            ra[j1][2], ra[j1][3], rbv[j0].y, rbv[j1].y);
        }
    }

    float* s = &g_s[0][0];
    #pragma unroll
    for (int mt = 0; mt < 2; mt++)
        #pragma unroll
        for (int t = 0; t < 2; t++) {
            int bA = b0 + mt * 16 + gr;
            int o  = t * 8 + 2 * gc;
            atomicAdd(&s[((size_t)bA * NC + c) * NO + o],     0.1f * sacc[mt][t][0]);
            atomicAdd(&s[((size_t)bA * NC + c) * NO + o + 1], 0.1f * sacc[mt][t][1]);
            atomicAdd(&s[((size_t)(bA + 8) * NC + c) * NO + o],     0.1f * sacc[mt][t][2]);
            atomicAdd(&s[((size_t)(bA + 8) * NC + c) * NO + o + 1], 0.1f * sacc[mt][t][3]);
        }
}

// ---------------------------------------------------------------------------
// Passes 1/2 (round-14 base): distributed exp + REDUCE-SCATTER logit
// reduction (3 shfl instead of 8 — each lane only needs its own row's sum).
// Z-warps between two barriers, W prefetch, k16 z-MMA unchanged.
// grid 512, occ 2.
// ---------------------------------------------------------------------------
template <int PASS>
__global__ __launch_bounds__(NTHREADS, 2) void pass_kernel()
{
    __shared__ uint4 xs[RCH * 32];
    __shared__ float sm_e[2][NC][32];
    __shared__ float sm_rz[2][32];

    const int tid  = threadIdx.x;
    const int lane = tid & 31;
    const int c    = tid >> 5;
    const int b0   = blockIdx.x * 32;
    const int gr   = lane >> 2;
    const int gc   = lane & 3;
    const int r0   = blockIdx.y * RCH;

    const float LOG2E = 1.4426950408889634f;

    // Prologue: V2[mt][ab][t] = LOG2E * sum_slot squash(s_slot)[b][c][o..o+1]
    float2 V2[2][2][2];
    #pragma unroll
    for (int mt = 0; mt < 2; mt++)
        #pragma unroll
        for (int ab = 0; ab < 2; ab++) {
            V2[mt][ab][0] = make_float2(0.f, 0.f);
            V2[mt][ab][1] = make_float2(0.f, 0.f);
            int b = b0 + mt * 16 + gr + ab * 8;
            const float* sb0 = &g_s[0][((size_t)b * NC + c) * NO];
            #pragma unroll
            for (int slot = 0; slot < PASS; slot++) {
                const float* sp = sb0 + (size_t)slot * (NB * NC * NO);
                float2 s0 = __ldg((const float2*)(sp + 2 * gc));
                float2 s1 = __ldg((const float2*)(sp + 8 + 2 * gc));
                float part = s0.x * s0.x + s0.y * s0.y
                           + s1.x * s1.x + s1.y * s1.y;
                part += __shfl_xor_sync(0xffffffffu, part, 1);
                part += __shfl_xor_sync(0xffffffffu, part, 2);
                float scale = (part / (1.0f + part)) * rsqrtf(part + 1e-8f)
                            * LOG2E;
                V2[mt][ab][0].x += scale * s0.x;
                V2[mt][ab][0].y += scale * s0.y;
                V2[mt][ab][1].x += scale * s1.x;
                V2[mt][ab][1].y += scale * s1.y;
            }
        }

    float sacc[2][2][4];
    #pragma unroll
    for (int mt = 0; mt < 2; mt++)
        #pragma unroll
        for (int t = 0; t < 2; t++)
            #pragma unroll
            for (int j = 0; j < 4; j++) sacc[mt][t][j] = 0.0f;

    const unsigned xs_base = (unsigned)__cvta_generic_to_shared(xs);
    const uint2* wbc = g_wht2 + (size_t)c * NR * 32;

    for (int i = tid; i < 32 * RCH; i += NTHREADS) {
        int b = i >> 6, r = i & (RCH - 1);
        xs[r * 32 + (b ^ (r & 7))] =
            __ldg(&g_xh[(size_t)(b0 + b) * NR + r0 + r]);
    }
    __syncthreads();

    // lane-owned row for the distributed exp (rid == gc)
    const int row_mine = (gc >> 1) * 16 + gr + (gc & 1) * 8;

    // preload W fragments for r-pair 0
    uint2 rbv[2];
    rbv[0] = __ldg(&wbc[(size_t)r0 * 32 + lane]);
    rbv[1] = __ldg(&wbc[(size_t)(r0 + 1) * 32 + lane]);

    #pragma unroll 1
    for (int rr = 0; rr < RCH; rr += 2) {
        // prefetch next r-pair's W BEFORE the softmax/barriers
        const int rn = (rr + 2 < RCH) ? rr + 2 : rr;
        uint2 rbn0 = __ldg(&wbc[(size_t)(r0 + rn) * 32 + lane]);
        uint2 rbn1 = __ldg(&wbc[(size_t)(r0 + rn + 1) * 32 + lane]);

        unsigned ra[2][4];
        #pragma unroll
        for (int j = 0; j < 2; j++) {
            const int rj = rr + j;
            unsigned amat =
                xs_base + (unsigned)(rj * 32 + (lane ^ (rj & 7))) * 16;
            asm volatile(
                "ldmatrix.sync.aligned.m8n8.x4.shared.b16 "
                "{%0,%1,%2,%3}, [%4];\n"
                : "=r"(ra[j][0]), "=r"(ra[j][1]),
                  "=r"(ra[j][2]), "=r"(ra[j][3]) : "r"(amat));
        }

        // u via MMA; reduce-scatter over the quad: each lane ends with ONLY
        // its own row's logit (3 shfl) -> one exp -> one conflict-free STS.
        #pragma unroll
        for (int j = 0; j < 2; j++) {
            float d[2][2][4];
            mma_16n8k8(d[0][0], ra[j][0], ra[j][1], rbv[j].x);
            mma_16n8k8(d[0][1], ra[j][0], ra[j][1], rbv[j].y);
            mma_16n8k8(d[1][0], ra[j][2], ra[j][3], rbv[j].x);
            mma_16n8k8(d[1][1], ra[j][2], ra[j][3], rbv[j].y);

            // partials for rows rid = 0..3  (rid = mt*2 + ab; own rid == gc)
            float p0 = d[0][0][0] * V2[0][0][0].x + d[0][0][1] * V2[0][0][0].y
                     + d[0][1][0] * V2[0][0][1].x + d[0][1][1] * V2[0][0][1].y;
            float p1 = d[0][0][2] * V2[0][1][0].x + d[0][0][3] * V2[0][1][0].y
                     + d[0][1][2] * V2[0][1][1].x + d[0][1][3] * V2[0][1][1].y;
            float p2 = d[1][0][0] * V2[1][0][0].x + d[1][0][1] * V2[1][0][0].y
                     + d[1][1][0] * V2[1][0][1].x + d[1][1][1] * V2[1][0][1].y;
            float p3 = d[1][0][2] * V2[1][1][0].x + d[1][0][3] * V2[1][1][0].y
                     + d[1][1][2] * V2[1][1][1].x + d[1][1][3] * V2[1][1][1].y;

            // step 1 (xor 1): keep rids with bit0 == (gc&1)
            float keepA = (gc & 1) ? p1 : p0;   // rid = (gc&1)
            float keepB = (gc & 1) ? p3 : p2;   // rid = 2 + (gc&1)
            float sendA = (gc & 1) ? p0 : p1;   // partner's rids
            float sendB = (gc & 1) ? p2 : p3;
            keepA += __shfl_xor_sync(0xffffffffu, sendA, 1);
            keepB += __shfl_xor_sync(0xffffffffu, sendB, 1);
            // step 2 (xor 2): keep rid with bit1 == (gc>>1)
            float keep = (gc & 2) ? keepB : keepA;
            float send = (gc & 2) ? keepA : keepB;
            keep += __shfl_xor_sync(0xffffffffu, send, 2);

            sm_e[j][c][row_mine] = exp2f(keep);
        }
        __syncthreads();

        if (tid < 64) {
            int j = tid >> 5, bb = tid & 31;
            float Z = 0.0f;
            #pragma unroll
            for (int k = 0; k < NC; k++) Z += sm_e[j][k][bb];
            sm_rz[j][bb] = __fdividef(1.0f, Z);
        }
        __syncthreads();

        // z = w * x fragments (w = e * rz from smem); k16 z-MMA
        unsigned z[2][4];
        #pragma unroll
        for (int j = 0; j < 2; j++) {
            __half2 wh[2][2];
            #pragma unroll
            for (int mt = 0; mt < 2; mt++)
                #pragma unroll
                for (int ab = 0; ab < 2; ab++) {
                    int row = mt * 16 + gr + ab * 8;
                    wh[mt][ab] = __float2half2_rn(
                        sm_e[j][c][row] * sm_rz[j][row]);
                }
            z[j][0] = hscale(ra[j][0], wh[0][0]);
            z[j][1] = hscale(ra[j][1], wh[0][1]);
            z[j][2] = hscale(ra[j][2], wh[1][0]);
            z[j][3] = hscale(ra[j][3], wh[1][1]);
        }
        mma_16n8k16_acc(sacc[0][0], z[0][0], z[0][1], z[1][0], z[1][1],
                        rbv[0].x, rbv[1].x);
        mma_16n8k16_acc(sacc[0][1], z[0][0], z[0][1], z[1][0], z[1][1],
                        rbv[0].y, rbv[1].y);
        mma_16n8k16_acc(sacc[1][0], z[0][2], z[0][3], z[1][2], z[1][3],
                        rbv[0].x, rbv[1].x);
        mma_16n8k16_acc(sacc[1][1], z[0][2], z[0][3], z[1][2], z[1][3],
                        rbv[0].y, rbv[1].y);

        rbv[0] = rbn0;
        rbv[1] = rbn1;
    }

    float* s = &g_s[PASS][0];
    #pragma unroll
    for (int mt = 0; mt < 2; mt++)
        #pragma unroll
        for (int t = 0; t < 2; t++) {
            int bA = b0 + mt * 16 + gr;
            int o  = t * 8 + 2 * gc;
            atomicAdd(&s[((size_t)bA * NC + c) * NO + o],     sacc[mt][t][0]);
            atomicAdd(&s[((size_t)bA * NC + c) * NO + o + 1], sacc[mt][t][1]);
            atomicAdd(&s[((size_t)(bA + 8) * NC + c) * NO + o],     sacc[mt][t][2]);
            atomicAdd(&s[((size_t)(bA + 8) * NC + c) * NO + o + 1], sacc[mt][t][3]);
        }
}

// Final output: v2 = squash(s2)
__global__ void squash_out_kernel(float* __restrict__ out) {
    int idx = blockIdx.x * blockDim.x + threadIdx.x;
    if (idx >= NB * NC) return;

    const float* s = &g_s[2][idx * NO];
    float sv[NO];
    float sq = 0.0f;
    #pragma unroll
    for (int q = 0; q < 4; q++) {
        float4 v = *(const float4*)(s + q * 4);
        sv[q * 4 + 0] = v.x; sv[q * 4 + 1] = v.y;
        sv[q * 4 + 2] = v.z; sv[q * 4 + 3] = v.w;
        sq += v.x * v.x + v.y * v.y + v.z * v.z + v.w * v.w;
    }
    float scale = (sq / (1.0f + sq)) * rsqrtf(sq + 1e-8f);
    #pragma unroll
    for (int o = 0; o < NO; o++) out[idx * NO + o] = scale * sv[o];
}

extern "C" void kernel_launch(void* const* d_in, const int* in_sizes, int n_in,
                              void* d_out, int out_size) {
    const float* x = (const float*)d_in[0];   // [128, 8192, 8]
    const float* W = (const float*)d_in[1];   // [10, 8192, 8, 16]
    float* out = (float*)d_out;               // [128, 10, 16]

    conv_w_kernel<<<(NC * NR * 32 + 255) / 256, 256>>>(W);

    dim3 grid(NB / 32, NR / RCH);             // (4, 128) = 512 blocks
    dim3 sq_grid((NB * NC + 255) / 256);

    pass0_kernel<<<grid, NTHREADS>>>(x);
    pass_kernel<1><<<grid, NTHREADS>>>();
    pass_kernel<2><<<grid, NTHREADS>>>();
    squash_out_kernel<<<sq_grid, 256>>>(out);
}

// round 17
// speedup vs baseline: 1.2315x; 1.0357x over previous
#include <cuda_runtime.h>
#include <cuda_fp16.h>
#include <cstdint>

// Problem constants
#define NB 128
#define NC 10
#define NR 8192
#define NI 8
#define NO 16

#define RCH 64        // r per block (single smem stage)
#define NTHREADS 320  // 10 warps, warp == class c

// Scratch (no cudaMalloc allowed)
__device__ float g_s[3][NB * NC * NO];
__device__ uint4 g_xh[(size_t)NB * NR];         // x fp16: [b][r][8i]
// W fragments pre-packed per (c, r, lane): .x = B-frag word n-tile0, .y = n-tile1
__device__ uint2 g_wht2[(size_t)NC * NR * 32];

// W [C,R,I,O] f32 -> per-lane packed B fragments. Also zeroes g_s.
__global__ void conv_w_kernel(const float* __restrict__ W) {
    int idx = blockIdx.x * blockDim.x + threadIdx.x;   // over NC*NR*32
    if (idx < 3 * NB * NC * NO) (&g_s[0][0])[idx] = 0.0f;
    if (idx >= NC * NR * 32) return;
    int lane = idx & 31;
    int rc   = idx >> 5;                               // c*NR + r
    int gr = lane >> 2, gc = lane & 3;
    const float* base = W + (size_t)rc * (NI * NO);
    float a0 = __ldg(base + (2 * gc) * NO + gr);
    float a1 = __ldg(base + (2 * gc + 1) * NO + gr);
    float b0 = __ldg(base + (2 * gc) * NO + gr + 8);
    float b1 = __ldg(base + (2 * gc + 1) * NO + gr + 8);
    __half2 h0 = __floats2half2_rn(a0, a1);
    __half2 h1 = __floats2half2_rn(b0, b1);
    uint2 v;
    v.x = *(unsigned*)&h0;
    v.y = *(unsigned*)&h1;
    g_wht2[idx] = v;
}

__device__ __forceinline__ void mma_16n8k8(float d[4], unsigned a0, unsigned a1,
                                           unsigned b0) {
    float z = 0.0f;
    asm volatile(
        "mma.sync.aligned.m16n8k8.row.col.f32.f16.f16.f32 "
        "{%0,%1,%2,%3}, {%4,%5}, {%6}, {%7,%8,%9,%10};\n"
        : "=f"(d[0]), "=f"(d[1]), "=f"(d[2]), "=f"(d[3])
        : "r"(a0), "r"(a1), "r"(b0), "f"(z), "f"(z), "f"(z), "f"(z));
}

// k16 accumulate: two independent k8 blocks (two r's) in one MMA.
__device__ __forceinline__ void mma_16n8k16_acc(float d[4],
                                                unsigned a0, unsigned a1,
                                                unsigned a2, unsigned a3,
                                                unsigned b0, unsigned b1) {
    asm volatile(
        "mma.sync.aligned.m16n8k16.row.col.f32.f16.f16.f32 "
        "{%0,%1,%2,%3}, {%4,%5,%6,%7}, {%8,%9}, {%0,%1,%2,%3};\n"
        : "+f"(d[0]), "+f"(d[1]), "+f"(d[2]), "+f"(d[3])
        : "r"(a0), "r"(a1), "r"(a2), "r"(a3), "r"(b0), "r"(b1));
}

__device__ __forceinline__ __half2 u2h(unsigned v) {
    __half2 h;
    *reinterpret_cast<unsigned*>(&h) = v;
    return h;
}

__device__ __forceinline__ unsigned hscale(unsigned xw, unsigned whu) {
    __half2 r = __hmul2(u2h(xw), u2h(whu));
    return *reinterpret_cast<unsigned*>(&r);
}

__device__ __forceinline__ uint4 pack_x8(float4 a, float4 b) {
    __half2 h0 = __floats2half2_rn(a.x, a.y);
    __half2 h1 = __floats2half2_rn(a.z, a.w);
    __half2 h2 = __floats2half2_rn(b.x, b.y);
    __half2 h3 = __floats2half2_rn(b.z, b.w);
    uint4 v;
    v.x = *(unsigned*)&h0; v.y = *(unsigned*)&h1;
    v.z = *(unsigned*)&h2; v.w = *(unsigned*)&h3;
    return v;
}

// ---------------------------------------------------------------------------
// Pass 0: uniform weights -> s0 = 0.1 * sum_r u. k16 MMA accumulation.
// Converts x to fp16 (writes g_xh) while staging. grid 512, occ 3.
// ---------------------------------------------------------------------------
__global__ __launch_bounds__(NTHREADS, 3) void pass0_kernel(
    const float* __restrict__ x)
{
    __shared__ uint4 xs[RCH * 32];          // x tile [r][b] swizzled (32 KB)

    const int tid  = threadIdx.x;
    const int lane = tid & 31;
    const int c    = tid >> 5;
    const int b0   = blockIdx.x * 32;
    const int gr   = lane >> 2;
    const int gc   = lane & 3;
    const int r0   = blockIdx.y * RCH;

    float sacc[2][2][4];
    #pragma unroll
    for (int mt = 0; mt < 2; mt++)
        #pragma unroll
        for (int t = 0; t < 2; t++)
            #pragma unroll
            for (int j = 0; j < 4; j++) sacc[mt][t][j] = 0.0f;

    const unsigned xs_base = (unsigned)__cvta_generic_to_shared(xs);
    const uint2* wbc = g_wht2 + (size_t)c * NR * 32;

    for (int i = tid; i < 32 * RCH; i += NTHREADS) {
        int b = i >> 6, r = i & (RCH - 1);
        size_t idx = (size_t)(b0 + b) * NR + r0 + r;
        const float4* p = (const float4*)x + idx * 2;
        uint4 v = pack_x8(__ldg(p), __ldg(p + 1));
        xs[r * 32 + (b ^ (r & 7))] = v;
        g_xh[idx] = v;                      // feed passes 1/2
    }
    __syncthreads();

    #pragma unroll 1
    for (int rr = 0; rr < RCH; rr += 4) {
        unsigned ra[4][4];
        uint2 rbv[4];
        #pragma unroll
        for (int j = 0; j < 4; j++) {
            const int rj = rr + j;
            unsigned amat =
                xs_base + (unsigned)(rj * 32 + (lane ^ (rj & 7))) * 16;
            asm volatile(
                "ldmatrix.sync.aligned.m8n8.x4.shared.b16 "
                "{%0,%1,%2,%3}, [%4];\n"
                : "=r"(ra[j][0]), "=r"(ra[j][1]),
                  "=r"(ra[j][2]), "=r"(ra[j][3]) : "r"(amat));
            rbv[j] = __ldg(&wbc[(size_t)(r0 + rj) * 32 + lane]);
        }
        #pragma unroll
        for (int p = 0; p < 2; p++) {       // r-pairs (j=2p, 2p+1)
            int j0 = 2 * p, j1 = 2 * p + 1;
            mma_16n8k16_acc(sacc[0][0], ra[j0][0], ra[j0][1],
                            ra[j1][0], ra[j1][1], rbv[j0].x, rbv[j1].x);
            mma_16n8k16_acc(sacc[0][1], ra[j0][0], ra[j0][1],
                            ra[j1][0], ra[j1][1], rbv[j0].y, rbv[j1].y);
            mma_16n8k16_acc(sacc[1][0], ra[j0][2], ra[j0][3],
                            ra[j1][2], ra[j1][3], rbv[j0].x, rbv[j1].x);
            mma_16n8k16_acc(sacc[1][1], ra[j0][2], ra[j0][3],
                            ra[j1][2], ra[j1][3], rbv[j0].y, rbv[j1].y);
        }
    }

    float* s = &g_s[0][0];
    #pragma unroll
    for (int mt = 0; mt < 2; mt++)
        #pragma unroll
        for (int t = 0; t < 2; t++) {
            int bA = b0 + mt * 16 + gr;
            int o  = t * 8 + 2 * gc;
            atomicAdd(&s[((size_t)bA * NC + c) * NO + o],     0.1f * sacc[mt][t][0]);
            atomicAdd(&s[((size_t)bA * NC + c) * NO + o + 1], 0.1f * sacc[mt][t][1]);
            atomicAdd(&s[((size_t)(bA + 8) * NC + c) * NO + o],     0.1f * sacc[mt][t][2]);
            atomicAdd(&s[((size_t)(bA + 8) * NC + c) * NO + o + 1], 0.1f * sacc[mt][t][3]);
        }
}

// ---------------------------------------------------------------------------
// Passes 1/2 (round-15 base): distributed exp + reduce-scatter logits.
// NEW: the Z-warps now produce pre-packed half2 weights sm_w[j][c][row]
// (w = e*rz, one CVT each) for ALL classes, so consumer warps form z with
// just 4 LDS per j — no FMUL/CVT on the consumer path. grid 512, occ 2.
// ---------------------------------------------------------------------------
template <int PASS>
__global__ __launch_bounds__(NTHREADS, 2) void pass_kernel()
{
    __shared__ uint4 xs[RCH * 32];
    __shared__ float sm_e[2][NC][32];
    __shared__ unsigned sm_w[2][NC][32];   // pre-packed half2 weights

    const int tid  = threadIdx.x;
    const int lane = tid & 31;
    const int c    = tid >> 5;
    const int b0   = blockIdx.x * 32;
    const int gr   = lane >> 2;
    const int gc   = lane & 3;
    const int r0   = blockIdx.y * RCH;

    const float LOG2E = 1.4426950408889634f;

    // Prologue: V2[mt][ab][t] = LOG2E * sum_slot squash(s_slot)[b][c][o..o+1]
    float2 V2[2][2][2];
    #pragma unroll
    for (int mt = 0; mt < 2; mt++)
        #pragma unroll
        for (int ab = 0; ab < 2; ab++) {
            V2[mt][ab][0] = make_float2(0.f, 0.f);
            V2[mt][ab][1] = make_float2(0.f, 0.f);
            int b = b0 + mt * 16 + gr + ab * 8;
            const float* sb0 = &g_s[0][((size_t)b * NC + c) * NO];
            #pragma unroll
            for (int slot = 0; slot < PASS; slot++) {
                const float* sp = sb0 + (size_t)slot * (NB * NC * NO);
                float2 s0 = __ldg((const float2*)(sp + 2 * gc));
                float2 s1 = __ldg((const float2*)(sp + 8 + 2 * gc));
                float part = s0.x * s0.x + s0.y * s0.y
                           + s1.x * s1.x + s1.y * s1.y;
                part += __shfl_xor_sync(0xffffffffu, part, 1);
                part += __shfl_xor_sync(0xffffffffu, part, 2);
                float scale = (part / (1.0f + part)) * rsqrtf(part + 1e-8f)
                            * LOG2E;
                V2[mt][ab][0].x += scale * s0.x;
                V2[mt][ab][0].y += scale * s0.y;
                V2[mt][ab][1].x += scale * s1.x;
                V2[mt][ab][1].y += scale * s1.y;
            }
        }

    float sacc[2][2][4];
    #pragma unroll
    for (int mt = 0; mt < 2; mt++)
        #pragma unroll
        for (int t = 0; t < 2; t++)
            #pragma unroll
            for (int j = 0; j < 4; j++) sacc[mt][t][j] = 0.0f;

    const unsigned xs_base = (unsigned)__cvta_generic_to_shared(xs);
    const uint2* wbc = g_wht2 + (size_t)c * NR * 32;

    for (int i = tid; i < 32 * RCH; i += NTHREADS) {
        int b = i >> 6, r = i & (RCH - 1);
        xs[r * 32 + (b ^ (r & 7))] =
            __ldg(&g_xh[(size_t)(b0 + b) * NR + r0 + r]);
    }
    __syncthreads();

    // lane-owned row for the distributed exp (rid == gc)
    const int row_mine = (gc >> 1) * 16 + gr + (gc & 1) * 8;

    // preload W fragments for r-pair 0
    uint2 rbv[2];
    rbv[0] = __ldg(&wbc[(size_t)r0 * 32 + lane]);
    rbv[1] = __ldg(&wbc[(size_t)(r0 + 1) * 32 + lane]);

    #pragma unroll 1
    for (int rr = 0; rr < RCH; rr += 2) {
        // prefetch next r-pair's W BEFORE the softmax/barriers
        const int rn = (rr + 2 < RCH) ? rr + 2 : rr;
        uint2 rbn0 = __ldg(&wbc[(size_t)(r0 + rn) * 32 + lane]);
        uint2 rbn1 = __ldg(&wbc[(size_t)(r0 + rn + 1) * 32 + lane]);

        unsigned ra[2][4];
        #pragma unroll
        for (int j = 0; j < 2; j++) {
            const int rj = rr + j;
            unsigned amat =
                xs_base + (unsigned)(rj * 32 + (lane ^ (rj & 7))) * 16;
            asm volatile(
                "ldmatrix.sync.aligned.m8n8.x4.shared.b16 "
                "{%0,%1,%2,%3}, [%4];\n"
                : "=r"(ra[j][0]), "=r"(ra[j][1]),
                  "=r"(ra[j][2]), "=r"(ra[j][3]) : "r"(amat));
        }

        // u via MMA; reduce-scatter over the quad: each lane ends with ONLY
        // its own row's logit (3 shfl) -> one exp -> one conflict-free STS.
        #pragma unroll
        for (int j = 0; j < 2; j++) {
            float d[2][2][4];
            mma_16n8k8(d[0][0], ra[j][0], ra[j][1], rbv[j].x);
            mma_16n8k8(d[0][1], ra[j][0], ra[j][1], rbv[j].y);
            mma_16n8k8(d[1][0], ra[j][2], ra[j][3], rbv[j].x);
            mma_16n8k8(d[1][1], ra[j][2], ra[j][3], rbv[j].y);

            // partials for rows rid = 0..3  (rid = mt*2 + ab; own rid == gc)
            float p0 = d[0][0][0] * V2[0][0][0].x + d[0][0][1] * V2[0][0][0].y
                     + d[0][1][0] * V2[0][0][1].x + d[0][1][1] * V2[0][0][1].y;
            float p1 = d[0][0][2] * V2[0][1][0].x + d[0][0][3] * V2[0][1][0].y
                     + d[0][1][2] * V2[0][1][1].x + d[0][1][3] * V2[0][1][1].y;
            float p2 = d[1][0][0] * V2[1][0][0].x + d[1][0][1] * V2[1][0][0].y
                     + d[1][1][0] * V2[1][0][1].x + d[1][1][1] * V2[1][0][1].y;
            float p3 = d[1][0][2] * V2[1][1][0].x + d[1][0][3] * V2[1][1][0].y
                     + d[1][1][2] * V2[1][1][1].x + d[1][1][3] * V2[1][1][1].y;

            // step 1 (xor 1): keep rids with bit0 == (gc&1)
            float keepA = (gc & 1) ? p1 : p0;   // rid = (gc&1)
            float keepB = (gc & 1) ? p3 : p2;   // rid = 2 + (gc&1)
            float sendA = (gc & 1) ? p0 : p1;   // partner's rids
            float sendB = (gc & 1) ? p2 : p3;
            keepA += __shfl_xor_sync(0xffffffffu, sendA, 1);
            keepB += __shfl_xor_sync(0xffffffffu, sendB, 1);
            // step 2 (xor 2): keep rid with bit1 == (gc>>1)
            float keep = (gc & 2) ? keepB : keepA;
            float send = (gc & 2) ? keepA : keepB;
            keep += __shfl_xor_sync(0xffffffffu, send, 2);

            sm_e[j][c][row_mine] = exp2f(keep);
        }
        __syncthreads();

        // Z-warps: Z, rz, then PRE-PACKED half2 weights for all 10 classes
        if (tid < 64) {
            int j = tid >> 5, bb = tid & 31;
            float ev[NC];
            float Z = 0.0f;
            #pragma unroll
            for (int k = 0; k < NC; k++) {
                ev[k] = sm_e[j][k][bb];
                Z += ev[k];
            }
            float rz = __fdividef(1.0f, Z);
            #pragma unroll
            for (int k = 0; k < NC; k++) {
                __half2 h = __float2half2_rn(ev[k] * rz);
                sm_w[j][k][bb] = *reinterpret_cast<unsigned*>(&h);
            }
        }
        __syncthreads();

        // z = w * x fragments (w pre-packed in smem); k16 z-MMA
        unsigned z[2][4];
        #pragma unroll
        for (int j = 0; j < 2; j++) {
            unsigned w00 = sm_w[j][c][gr];
            unsigned w01 = sm_w[j][c][gr + 8];
            unsigned w10 = sm_w[j][c][gr + 16];
            unsigned w11 = sm_w[j][c][gr + 24];
            z[j][0] = hscale(ra[j][0], w00);
            z[j][1] = hscale(ra[j][1], w01);
            z[j][2] = hscale(ra[j][2], w10);
            z[j][3] = hscale(ra[j][3], w11);
        }
        mma_16n8k16_acc(sacc[0][0], z[0][0], z[0][1], z[1][0], z[1][1],
                        rbv[0].x, rbv[1].x);
        mma_16n8k16_acc(sacc[0][1], z[0][0], z[0][1], z[1][0], z[1][1],
                        rbv[0].y, rbv[1].y);
        mma_16n8k16_acc(sacc[1][0], z[0][2], z[0][3], z[1][2], z[1][3],
                        rbv[0].x, rbv[1].x);
        mma_16n8k16_acc(sacc[1][1], z[0][2], z[0][3], z[1][2], z[1][3],
                        rbv[0].y, rbv[1].y);

        rbv[0] = rbn0;
        rbv[1] = rbn1;
    }

    float* s = &g_s[PASS][0];
    #pragma unroll
    for (int mt = 0; mt < 2; mt++)
        #pragma unroll
        for (int t = 0; t < 2; t++) {
            int bA = b0 + mt * 16 + gr;
            int o  = t * 8 + 2 * gc;
            atomicAdd(&s[((size_t)bA * NC + c) * NO + o],     sacc[mt][t][0]);
            atomicAdd(&s[((size_t)bA * NC + c) * NO + o + 1], sacc[mt][t][1]);
            atomicAdd(&s[((size_t)(bA + 8) * NC + c) * NO + o],     sacc[mt][t][2]);
            atomicAdd(&s[((size_t)(bA + 8) * NC + c) * NO + o + 1], sacc[mt][t][3]);
        }
}

// Final output: v2 = squash(s2)
__global__ void squash_out_kernel(float* __restrict__ out) {
    int idx = blockIdx.x * blockDim.x + threadIdx.x;
    if (idx >= NB * NC) return;

    const float* s = &g_s[2][idx * NO];
    float sv[NO];
    float sq = 0.0f;
    #pragma unroll
    for (int q = 0; q < 4; q++) {
        float4 v = *(const float4*)(s + q * 4);
        sv[q * 4 + 0] = v.x; sv[q * 4 + 1] = v.y;
        sv[q * 4 + 2] = v.z; sv[q * 4 + 3] = v.w;
        sq += v.x * v.x + v.y * v.y + v.z * v.z + v.w * v.w;
    }
    float scale = (sq / (1.0f + sq)) * rsqrtf(sq + 1e-8f);
    #pragma unroll
    for (int o = 0; o < NO; o++) out[idx * NO + o] = scale * sv[o];
}

extern "C" void kernel_launch(void* const* d_in, const int* in_sizes, int n_in,
                              void* d_out, int out_size) {
    const float* x = (const float*)d_in[0];   // [128, 8192, 8]
    const float* W = (const float*)d_in[1];   // [10, 8192, 8, 16]
    float* out = (float*)d_out;               // [128, 10, 16]

    conv_w_kernel<<<(NC * NR * 32 + 255) / 256, 256>>>(W);

    dim3 grid(NB / 32, NR / RCH);             // (4, 128) = 512 blocks
    dim3 sq_grid((NB * NC + 255) / 256);

    pass0_kernel<<<grid, NTHREADS>>>(x);
    pass_kernel<1><<<grid, NTHREADS>>>();
    pass_kernel<2><<<grid, NTHREADS>>>();
    squash_out_kernel<<<sq_grid, 256>>>(out);
}